// round 1
// baseline (speedup 1.0000x reference)
#include <cuda_runtime.h>
#include <math.h>

// Problem dims (fixed)
#define BSZ 4096
#define HD  2048
#define ID  2048
#define NS  3
#define LN_EPS 1e-5f

// Scratch (static device globals; no dynamic alloc allowed)
__device__ float g_weighted[(size_t)BSZ * HD];
__device__ int   g_sel[BSZ];

// ---------------------------------------------------------------------------
// Kernel 1: gate logits + hard gumbel-softmax (numerically exact one-hot)
// ---------------------------------------------------------------------------
__global__ void gate_kernel(const float* __restrict__ prev_master,
                            const float* __restrict__ gumbel,
                            const float* __restrict__ gate_W,
                            const float* __restrict__ gate_b,
                            float* __restrict__ out_gate)
{
    int b   = blockIdx.x;
    int tid = threadIdx.x;   // 128 threads
    const float* row = prev_master + (size_t)b * HD;

    float p0 = 0.f, p1 = 0.f, p2 = 0.f;
    for (int h = tid * 4; h < HD; h += 128 * 4) {
        float4 v  = *(const float4*)(row + h);
        float4 w0 = *(const float4*)(gate_W + 0 * HD + h);
        float4 w1 = *(const float4*)(gate_W + 1 * HD + h);
        float4 w2 = *(const float4*)(gate_W + 2 * HD + h);
        p0 += v.x * w0.x + v.y * w0.y + v.z * w0.z + v.w * w0.w;
        p1 += v.x * w1.x + v.y * w1.y + v.z * w1.z + v.w * w1.w;
        p2 += v.x * w2.x + v.y * w2.y + v.z * w2.z + v.w * w2.w;
    }
    // warp reduce
    #pragma unroll
    for (int o = 16; o > 0; o >>= 1) {
        p0 += __shfl_down_sync(0xffffffffu, p0, o);
        p1 += __shfl_down_sync(0xffffffffu, p1, o);
        p2 += __shfl_down_sync(0xffffffffu, p2, o);
    }
    __shared__ float s0[4], s1[4], s2[4];
    int wid = tid >> 5, lid = tid & 31;
    if (lid == 0) { s0[wid] = p0; s1[wid] = p1; s2[wid] = p2; }
    __syncthreads();
    if (tid == 0) {
        float z0 = s0[0] + s0[1] + s0[2] + s0[3] + gate_b[0] + gumbel[b * 3 + 0];
        float z1 = s1[0] + s1[1] + s1[2] + s1[3] + gate_b[1] + gumbel[b * 3 + 1];
        float z2 = s2[0] + s2[1] + s2[2] + s2[3] + gate_b[2] + gumbel[b * 3 + 2];
        // argmax with first-max tie-break (matches jnp.argmax)
        int am = 0; float zm = z0;
        if (z1 > zm) { am = 1; zm = z1; }
        if (z2 > zm) { am = 2; }
        out_gate[b * 3 + 0] = (am == 0) ? 1.f : 0.f;
        out_gate[b * 3 + 1] = (am == 1) ? 1.f : 0.f;
        out_gate[b * 3 + 2] = (am == 2) ? 1.f : 0.f;
        g_sel[b] = am;
    }
}

// ---------------------------------------------------------------------------
// Tiled SGEMM core: 128x128 block tile, BK=16, 256 threads, 8x8 per thread.
// NT layout: C[m,n] = sum_k A[m,k]*B[n,k] (both row-major, K contiguous).
// ---------------------------------------------------------------------------
#define BM 128
#define BN 128
#define BK 16

// Kernel 2: sub-cell RNN.  acc over K = I (x @ W_ih^T) then K = H (h @ W_hh^T)
__global__ __launch_bounds__(256, 2)
void subcell_kernel(const float* __restrict__ x,
                    const float* __restrict__ prev_sub,
                    const float* __restrict__ W_ih,
                    const float* __restrict__ W_hh,
                    const float* __restrict__ b_ih,
                    const float* __restrict__ b_hh,
                    float* __restrict__ out_sub)
{
    int s  = blockIdx.z;
    int m0 = blockIdx.y * BM;
    int n0 = blockIdx.x * BN;

    const float* A0 = x;
    const float* A1 = prev_sub + (size_t)s * BSZ * HD;
    const float* B0 = W_ih + (size_t)s * HD * ID;
    const float* B1 = W_hh + (size_t)s * HD * HD;

    __shared__ float As[BK][BM];
    __shared__ float Bs[BK][BN];

    int tid  = threadIdx.x;
    int tx   = tid & 15;        // n direction
    int ty   = tid >> 4;        // m direction
    int lrow = tid >> 2;        // 0..63
    int lcol = (tid & 3) * 4;   // 0,4,8,12

    float acc[8][8];
    #pragma unroll
    for (int i = 0; i < 8; i++)
        #pragma unroll
        for (int j = 0; j < 8; j++) acc[i][j] = 0.f;

    for (int k0 = 0; k0 < ID + HD; k0 += BK) {
        const float* Ab; const float* Bb; int kk;
        if (k0 < ID) { Ab = A0; Bb = B0; kk = k0; }
        else         { Ab = A1; Bb = B1; kk = k0 - ID; }

        #pragma unroll
        for (int it = 0; it < 2; it++) {
            int r = lrow + it * 64;
            float4 av = *(const float4*)(Ab + (size_t)(m0 + r) * 2048 + kk + lcol);
            As[lcol + 0][r] = av.x; As[lcol + 1][r] = av.y;
            As[lcol + 2][r] = av.z; As[lcol + 3][r] = av.w;
            float4 bv = *(const float4*)(Bb + (size_t)(n0 + r) * 2048 + kk + lcol);
            Bs[lcol + 0][r] = bv.x; Bs[lcol + 1][r] = bv.y;
            Bs[lcol + 2][r] = bv.z; Bs[lcol + 3][r] = bv.w;
        }
        __syncthreads();

        #pragma unroll
        for (int k = 0; k < BK; k++) {
            float a[8], bb[8];
            *(float4*)&a[0]  = *(const float4*)&As[k][ty * 8];
            *(float4*)&a[4]  = *(const float4*)&As[k][ty * 8 + 4];
            *(float4*)&bb[0] = *(const float4*)&Bs[k][tx * 8];
            *(float4*)&bb[4] = *(const float4*)&Bs[k][tx * 8 + 4];
            #pragma unroll
            for (int i = 0; i < 8; i++)
                #pragma unroll
                for (int j = 0; j < 8; j++)
                    acc[i][j] += a[i] * bb[j];
        }
        __syncthreads();
    }

    // epilogue: bias + tanh, write new_sub; gather into weighted if selected
    #pragma unroll
    for (int i = 0; i < 8; i++) {
        int m   = m0 + ty * 8 + i;
        int sel = g_sel[m];
        float* orow = out_sub + ((size_t)s * BSZ + m) * HD;
        #pragma unroll
        for (int j = 0; j < 8; j++) {
            int n = n0 + tx * 8 + j;
            float v = tanhf(acc[i][j] + b_ih[s * HD + n] + b_hh[s * HD + n]);
            orow[n] = v;
            if (sel == s) g_weighted[(size_t)m * HD + n] = v;
        }
    }
}

// Kernel 3: fusion GEMM.  pre = prev_master + weighted @ fusion_W^T + fusion_b
// writes "pre" into out_master (LN kernel finishes in place).
__global__ __launch_bounds__(256, 2)
void fusion_kernel(const float* __restrict__ fusion_W,
                   const float* __restrict__ fusion_b,
                   const float* __restrict__ prev_master,
                   float* __restrict__ out_master)
{
    int m0 = blockIdx.y * BM;
    int n0 = blockIdx.x * BN;

    __shared__ float As[BK][BM];
    __shared__ float Bs[BK][BN];

    int tid  = threadIdx.x;
    int tx   = tid & 15;
    int ty   = tid >> 4;
    int lrow = tid >> 2;
    int lcol = (tid & 3) * 4;

    float acc[8][8];
    #pragma unroll
    for (int i = 0; i < 8; i++)
        #pragma unroll
        for (int j = 0; j < 8; j++) acc[i][j] = 0.f;

    for (int k0 = 0; k0 < HD; k0 += BK) {
        #pragma unroll
        for (int it = 0; it < 2; it++) {
            int r = lrow + it * 64;
            float4 av = *(const float4*)(g_weighted + (size_t)(m0 + r) * HD + k0 + lcol);
            As[lcol + 0][r] = av.x; As[lcol + 1][r] = av.y;
            As[lcol + 2][r] = av.z; As[lcol + 3][r] = av.w;
            float4 bv = *(const float4*)(fusion_W + (size_t)(n0 + r) * HD + k0 + lcol);
            Bs[lcol + 0][r] = bv.x; Bs[lcol + 1][r] = bv.y;
            Bs[lcol + 2][r] = bv.z; Bs[lcol + 3][r] = bv.w;
        }
        __syncthreads();

        #pragma unroll
        for (int k = 0; k < BK; k++) {
            float a[8], bb[8];
            *(float4*)&a[0]  = *(const float4*)&As[k][ty * 8];
            *(float4*)&a[4]  = *(const float4*)&As[k][ty * 8 + 4];
            *(float4*)&bb[0] = *(const float4*)&Bs[k][tx * 8];
            *(float4*)&bb[4] = *(const float4*)&Bs[k][tx * 8 + 4];
            #pragma unroll
            for (int i = 0; i < 8; i++)
                #pragma unroll
                for (int j = 0; j < 8; j++)
                    acc[i][j] += a[i] * bb[j];
        }
        __syncthreads();
    }

    #pragma unroll
    for (int i = 0; i < 8; i++) {
        int m = m0 + ty * 8 + i;
        #pragma unroll
        for (int j = 0; j < 8; j++) {
            int n = n0 + tx * 8 + j;
            out_master[(size_t)m * HD + n] =
                acc[i][j] + fusion_b[n] + prev_master[(size_t)m * HD + n];
        }
    }
}

// ---------------------------------------------------------------------------
// Kernel 4: in-place LayerNorm + sigmoid over rows of out_master
// ---------------------------------------------------------------------------
__global__ void ln_kernel(float* __restrict__ out_master,
                          const float* __restrict__ ln_g,
                          const float* __restrict__ ln_b)
{
    int b   = blockIdx.x;
    int tid = threadIdx.x;   // 256
    float* row = out_master + (size_t)b * HD;

    float v[8];
    float sum = 0.f, sq = 0.f;
    #pragma unroll
    for (int i = 0; i < 2; i++) {
        float4 t = *(const float4*)(row + tid * 4 + i * 1024);
        v[i * 4 + 0] = t.x; v[i * 4 + 1] = t.y; v[i * 4 + 2] = t.z; v[i * 4 + 3] = t.w;
        sum += t.x + t.y + t.z + t.w;
        sq  += t.x * t.x + t.y * t.y + t.z * t.z + t.w * t.w;
    }
    #pragma unroll
    for (int o = 16; o > 0; o >>= 1) {
        sum += __shfl_down_sync(0xffffffffu, sum, o);
        sq  += __shfl_down_sync(0xffffffffu, sq, o);
    }
    __shared__ float ssum[8], ssq[8];
    int wid = tid >> 5, lid = tid & 31;
    if (lid == 0) { ssum[wid] = sum; ssq[wid] = sq; }
    __syncthreads();
    __shared__ float s_mu, s_rstd;
    if (tid == 0) {
        float ts = 0.f, tq = 0.f;
        #pragma unroll
        for (int w = 0; w < 8; w++) { ts += ssum[w]; tq += ssq[w]; }
        float mu  = ts / (float)HD;
        float var = tq / (float)HD - mu * mu;
        s_mu = mu;
        s_rstd = rsqrtf(var + LN_EPS);
    }
    __syncthreads();
    float mu = s_mu, rstd = s_rstd;
    #pragma unroll
    for (int i = 0; i < 2; i++) {
        int h0 = tid * 4 + i * 1024;
        float4 o;
        float n0 = (v[i * 4 + 0] - mu) * rstd * ln_g[h0 + 0] + ln_b[h0 + 0];
        float n1 = (v[i * 4 + 1] - mu) * rstd * ln_g[h0 + 1] + ln_b[h0 + 1];
        float n2 = (v[i * 4 + 2] - mu) * rstd * ln_g[h0 + 2] + ln_b[h0 + 2];
        float n3 = (v[i * 4 + 3] - mu) * rstd * ln_g[h0 + 3] + ln_b[h0 + 3];
        o.x = 1.f / (1.f + expf(-n0));
        o.y = 1.f / (1.f + expf(-n1));
        o.z = 1.f / (1.f + expf(-n2));
        o.w = 1.f / (1.f + expf(-n3));
        *(float4*)(row + h0) = o;
    }
}

// ---------------------------------------------------------------------------
// Launch
// ---------------------------------------------------------------------------
extern "C" void kernel_launch(void* const* d_in, const int* in_sizes, int n_in,
                              void* d_out, int out_size)
{
    const float* x           = (const float*)d_in[0];   // [B, I]
    const float* prev_master = (const float*)d_in[1];   // [B, H]
    const float* prev_sub    = (const float*)d_in[2];   // [S, B, H]
    const float* gumbel      = (const float*)d_in[3];   // [B, S]
    const float* W_ih        = (const float*)d_in[4];   // [S, H, I]
    const float* W_hh        = (const float*)d_in[5];   // [S, H, H]
    const float* b_ih        = (const float*)d_in[6];   // [S, H]
    const float* b_hh        = (const float*)d_in[7];   // [S, H]
    const float* gate_W      = (const float*)d_in[8];   // [S, H]
    const float* gate_b      = (const float*)d_in[9];   // [S]
    const float* fusion_W    = (const float*)d_in[10];  // [H, H]
    const float* fusion_b    = (const float*)d_in[11];  // [H]
    const float* ln_g        = (const float*)d_in[12];  // [H]
    const float* ln_b        = (const float*)d_in[13];  // [H]

    float* out        = (float*)d_out;
    float* out_master = out;                                  // B*H
    float* out_gate   = out + (size_t)BSZ * HD;               // B*S
    float* out_sub    = out + (size_t)BSZ * HD + BSZ * NS;    // S*B*H

    gate_kernel<<<BSZ, 128>>>(prev_master, gumbel, gate_W, gate_b, out_gate);

    dim3 g2(HD / BN, BSZ / BM, NS);
    subcell_kernel<<<g2, 256>>>(x, prev_sub, W_ih, W_hh, b_ih, b_hh, out_sub);

    dim3 g3(HD / BN, BSZ / BM);
    fusion_kernel<<<g3, 256>>>(fusion_W, fusion_b, prev_master, out_master);

    ln_kernel<<<BSZ, 256>>>(out_master, ln_g, ln_b);
}

// round 3
// speedup vs baseline: 3.6764x; 3.6764x over previous
#include <cuda_runtime.h>
#include <math.h>
#include <stdint.h>

// Problem dims (fixed)
#define BSZ 4096
#define HD  2048
#define ID  2048
#define NS  3
#define LN_EPS 1e-5f

// GEMM tile config
#define BM 128
#define BN 128
#define BK 32
#define NTHREADS 128
#define ROWPAD 36                       // floats per smem row (32 + 4 pad)
#define STAGE_F (128 * ROWPAD)          // floats per operand stage
#define STAGE_B (STAGE_F * 4)           // 18432 bytes
#define SMEM_BYTES (4 * STAGE_B)        // A0,A1,B0,B1 = 73728

// Scratch (static device globals; no dynamic alloc allowed)
__device__ float g_weighted[(size_t)BSZ * HD];
__device__ int   g_sel[BSZ];

// ---------------------------------------------------------------------------
// helpers
// ---------------------------------------------------------------------------
__device__ __forceinline__ uint32_t smem_u32(const void* p) {
    uint32_t a;
    asm("{ .reg .u64 t; cvta.to.shared.u64 t, %1; cvt.u32.u64 %0, t; }"
        : "=r"(a) : "l"(p));
    return a;
}
__device__ __forceinline__ void cp16(uint32_t dst, const void* src) {
    asm volatile("cp.async.cg.shared.global [%0], [%1], 16;"
                 :: "r"(dst), "l"(src) : "memory");
}
__device__ __forceinline__ void cp_commit() {
    asm volatile("cp.async.commit_group;" ::: "memory");
}
template <int N> __device__ __forceinline__ void cp_wait() {
    asm volatile("cp.async.wait_group %0;" :: "n"(N) : "memory");
}
__device__ __forceinline__ uint32_t f2tf32(float x) {
    uint32_t r;
    asm("cvt.rna.tf32.f32 %0, %1;" : "=r"(r) : "f"(x));
    return r;
}
__device__ __forceinline__ void mma_tf32(float c[4], uint32_t a0, uint32_t a1,
                                         uint32_t a2, uint32_t a3,
                                         uint32_t b0, uint32_t b1) {
    asm volatile(
        "mma.sync.aligned.m16n8k8.row.col.f32.tf32.tf32.f32 "
        "{%0,%1,%2,%3}, {%4,%5,%6,%7}, {%8,%9}, {%0,%1,%2,%3};"
        : "+f"(c[0]), "+f"(c[1]), "+f"(c[2]), "+f"(c[3])
        : "r"(a0), "r"(a1), "r"(a2), "r"(a3), "r"(b0), "r"(b1));
}

// ---------------------------------------------------------------------------
// Kernel 1: gate logits + hard gumbel-softmax (numerically exact one-hot)
// ---------------------------------------------------------------------------
__global__ void gate_kernel(const float* __restrict__ prev_master,
                            const float* __restrict__ gumbel,
                            const float* __restrict__ gate_W,
                            const float* __restrict__ gate_b,
                            float* __restrict__ out_gate)
{
    int b   = blockIdx.x;
    int tid = threadIdx.x;   // 128 threads
    const float* row = prev_master + (size_t)b * HD;

    float p0 = 0.f, p1 = 0.f, p2 = 0.f;
    for (int h = tid * 4; h < HD; h += 128 * 4) {
        float4 v  = *(const float4*)(row + h);
        float4 w0 = *(const float4*)(gate_W + 0 * HD + h);
        float4 w1 = *(const float4*)(gate_W + 1 * HD + h);
        float4 w2 = *(const float4*)(gate_W + 2 * HD + h);
        p0 += v.x * w0.x + v.y * w0.y + v.z * w0.z + v.w * w0.w;
        p1 += v.x * w1.x + v.y * w1.y + v.z * w1.z + v.w * w1.w;
        p2 += v.x * w2.x + v.y * w2.y + v.z * w2.z + v.w * w2.w;
    }
    #pragma unroll
    for (int o = 16; o > 0; o >>= 1) {
        p0 += __shfl_down_sync(0xffffffffu, p0, o);
        p1 += __shfl_down_sync(0xffffffffu, p1, o);
        p2 += __shfl_down_sync(0xffffffffu, p2, o);
    }
    __shared__ float s0[4], s1[4], s2[4];
    int wid = tid >> 5, lid = tid & 31;
    if (lid == 0) { s0[wid] = p0; s1[wid] = p1; s2[wid] = p2; }
    __syncthreads();
    if (tid == 0) {
        float z0 = s0[0] + s0[1] + s0[2] + s0[3] + gate_b[0] + gumbel[b * 3 + 0];
        float z1 = s1[0] + s1[1] + s1[2] + s1[3] + gate_b[1] + gumbel[b * 3 + 1];
        float z2 = s2[0] + s2[1] + s2[2] + s2[3] + gate_b[2] + gumbel[b * 3 + 2];
        int am = 0; float zm = z0;
        if (z1 > zm) { am = 1; zm = z1; }
        if (z2 > zm) { am = 2; }
        out_gate[b * 3 + 0] = (am == 0) ? 1.f : 0.f;
        out_gate[b * 3 + 1] = (am == 1) ? 1.f : 0.f;
        out_gate[b * 3 + 2] = (am == 2) ? 1.f : 0.f;
        g_sel[b] = am;
    }
}

// ---------------------------------------------------------------------------
// tf32 mma.sync GEMM core (shared by subcell & fusion kernels)
// C[128,128] per CTA, 4 warps in 2x2 grid, warp tile 64x64.
// A: [B,K] row-major; W: [N,K] row-major (acts as col-major B). K contiguous.
// ---------------------------------------------------------------------------
struct GemmCtx {
    float* sm;          // dynamic smem base
    uint32_t sm32;      // shared addr of base
    int tid, lane, g, tg, wm0, wn0;
};

__device__ __forceinline__ void gemm_init(GemmCtx& cx, float* sm) {
    cx.sm   = sm;
    cx.sm32 = smem_u32(sm);
    cx.tid  = threadIdx.x;
    cx.lane = cx.tid & 31;
    cx.g    = cx.lane >> 2;
    cx.tg   = cx.lane & 3;
    int wid = cx.tid >> 5;
    cx.wm0  = (wid >> 1) * 64;
    cx.wn0  = (wid & 1) * 64;
}

// load one BK tile of A (rows m0..m0+127) and B (rows n0..n0+127) into stage sl
__device__ __forceinline__ void gemm_load(const GemmCtx& cx,
                                          const float* __restrict__ A, int m0,
                                          const float* __restrict__ Bw, int n0,
                                          int kc, int sl) {
    int r0 = cx.tid >> 3;          // 0..15
    int ch = (cx.tid & 7) * 4;     // float offset within row
    uint32_t abase = cx.sm32 + sl * STAGE_B;
    uint32_t bbase = cx.sm32 + 2 * STAGE_B + sl * STAGE_B;
    #pragma unroll
    for (int p = 0; p < 8; p++) {
        int r = r0 + p * 16;
        cp16(abase + (r * ROWPAD + ch) * 4, A  + (size_t)(m0 + r) * 2048 + kc + ch);
        cp16(bbase + (r * ROWPAD + ch) * 4, Bw + (size_t)(n0 + r) * 2048 + kc + ch);
    }
}

__device__ __forceinline__ void gemm_compute(const GemmCtx& cx, int sl,
                                             float c[4][8][4]) {
    const float* As = cx.sm + sl * STAGE_F;
    const float* Bs = cx.sm + 2 * STAGE_F + sl * STAGE_F;
    #pragma unroll
    for (int kk = 0; kk < BK; kk += 8) {
        uint32_t a[4][4], b[8][2];
        #pragma unroll
        for (int i = 0; i < 4; i++) {
            int m = cx.wm0 + i * 16 + cx.g;
            a[i][0] = f2tf32(As[m * ROWPAD + kk + cx.tg]);
            a[i][1] = f2tf32(As[(m + 8) * ROWPAD + kk + cx.tg]);
            a[i][2] = f2tf32(As[m * ROWPAD + kk + cx.tg + 4]);
            a[i][3] = f2tf32(As[(m + 8) * ROWPAD + kk + cx.tg + 4]);
        }
        #pragma unroll
        for (int j = 0; j < 8; j++) {
            int n = cx.wn0 + j * 8 + cx.g;
            b[j][0] = f2tf32(Bs[n * ROWPAD + kk + cx.tg]);
            b[j][1] = f2tf32(Bs[n * ROWPAD + kk + cx.tg + 4]);
        }
        #pragma unroll
        for (int i = 0; i < 4; i++)
            #pragma unroll
            for (int j = 0; j < 8; j++)
                mma_tf32(c[i][j], a[i][0], a[i][1], a[i][2], a[i][3],
                         b[j][0], b[j][1]);
    }
}

// ---------------------------------------------------------------------------
// Kernel 2: sub-cell RNN.  K = 4096 total (x@W_ih^T then h@W_hh^T), tanh epi.
// ---------------------------------------------------------------------------
__global__ __launch_bounds__(NTHREADS, 2)
void subcell_kernel(const float* __restrict__ x,
                    const float* __restrict__ prev_sub,
                    const float* __restrict__ W_ih,
                    const float* __restrict__ W_hh,
                    const float* __restrict__ b_ih,
                    const float* __restrict__ b_hh,
                    float* __restrict__ out_sub)
{
    extern __shared__ float sm[];
    GemmCtx cx; gemm_init(cx, sm);
    const int s  = blockIdx.z;
    const int m0 = blockIdx.y * BM;
    const int n0 = blockIdx.x * BN;

    const float* A0 = x;
    const float* A1 = prev_sub + (size_t)s * BSZ * HD;
    const float* B0 = W_ih + (size_t)s * HD * ID;
    const float* B1 = W_hh + (size_t)s * HD * HD;

    float c[4][8][4];
    #pragma unroll
    for (int i = 0; i < 4; i++)
        #pragma unroll
        for (int j = 0; j < 8; j++)
            #pragma unroll
            for (int q = 0; q < 4; q++) c[i][j][q] = 0.f;

    const int NT = 128;  // 64 tiles (x,W_ih) + 64 tiles (h,W_hh)
    auto tile_load = [&](int t, int sl) {
        if (t < 64) gemm_load(cx, A0, m0, B0, n0, t * BK, sl);
        else        gemm_load(cx, A1, m0, B1, n0, (t - 64) * BK, sl);
    };

    tile_load(0, 0); cp_commit();
    tile_load(1, 1); cp_commit();

    for (int t = 0; t < NT; t++) {
        cp_wait<1>();
        __syncthreads();
        int sl = t & 1;
        gemm_compute(cx, sl, c);
        __syncthreads();
        if (t + 2 < NT) tile_load(t + 2, sl);
        cp_commit();
    }

    // epilogue: bias + tanh -> out_sub; conditional gather into g_weighted
    const float* bi = b_ih + (size_t)s * HD;
    const float* bh = b_hh + (size_t)s * HD;
    #pragma unroll
    for (int i = 0; i < 4; i++) {
        int rlo = m0 + cx.wm0 + i * 16 + cx.g;
        int rhi = rlo + 8;
        int selo = g_sel[rlo], sehi = g_sel[rhi];
        float* olo = out_sub + ((size_t)s * BSZ + rlo) * HD;
        float* ohi = out_sub + ((size_t)s * BSZ + rhi) * HD;
        float* wlo = g_weighted + (size_t)rlo * HD;
        float* whi = g_weighted + (size_t)rhi * HD;
        #pragma unroll
        for (int j = 0; j < 8; j++) {
            int n = n0 + cx.wn0 + j * 8 + cx.tg * 2;
            float2 bv0 = *(const float2*)(bi + n);
            float2 bv1 = *(const float2*)(bh + n);
            float bs0 = bv0.x + bv1.x, bs1 = bv0.y + bv1.y;
            float2 vlo = make_float2(tanhf(c[i][j][0] + bs0),
                                     tanhf(c[i][j][1] + bs1));
            float2 vhi = make_float2(tanhf(c[i][j][2] + bs0),
                                     tanhf(c[i][j][3] + bs1));
            *(float2*)(olo + n) = vlo;
            *(float2*)(ohi + n) = vhi;
            if (selo == s) *(float2*)(wlo + n) = vlo;
            if (sehi == s) *(float2*)(whi + n) = vhi;
        }
    }
}

// ---------------------------------------------------------------------------
// Kernel 3: fusion GEMM.  pre = prev_master + weighted @ fusion_W^T + fusion_b
// ---------------------------------------------------------------------------
__global__ __launch_bounds__(NTHREADS, 2)
void fusion_kernel(const float* __restrict__ fusion_W,
                   const float* __restrict__ fusion_b,
                   const float* __restrict__ prev_master,
                   float* __restrict__ out_master)
{
    extern __shared__ float sm[];
    GemmCtx cx; gemm_init(cx, sm);
    const int m0 = blockIdx.y * BM;
    const int n0 = blockIdx.x * BN;

    float c[4][8][4];
    #pragma unroll
    for (int i = 0; i < 4; i++)
        #pragma unroll
        for (int j = 0; j < 8; j++)
            #pragma unroll
            for (int q = 0; q < 4; q++) c[i][j][q] = 0.f;

    const int NT = 64;
    gemm_load(cx, g_weighted, m0, fusion_W, n0, 0, 0);      cp_commit();
    gemm_load(cx, g_weighted, m0, fusion_W, n0, BK, 1);     cp_commit();

    for (int t = 0; t < NT; t++) {
        cp_wait<1>();
        __syncthreads();
        int sl = t & 1;
        gemm_compute(cx, sl, c);
        __syncthreads();
        if (t + 2 < NT) gemm_load(cx, g_weighted, m0, fusion_W, n0, (t + 2) * BK, sl);
        cp_commit();
    }

    // epilogue: + fusion_b + prev_master (pre-LN values)
    #pragma unroll
    for (int i = 0; i < 4; i++) {
        int rlo = m0 + cx.wm0 + i * 16 + cx.g;
        int rhi = rlo + 8;
        const float* plo = prev_master + (size_t)rlo * HD;
        const float* phi = prev_master + (size_t)rhi * HD;
        float* olo = out_master + (size_t)rlo * HD;
        float* ohi = out_master + (size_t)rhi * HD;
        #pragma unroll
        for (int j = 0; j < 8; j++) {
            int n = n0 + cx.wn0 + j * 8 + cx.tg * 2;
            float2 fb = *(const float2*)(fusion_b + n);
            float2 mlo = *(const float2*)(plo + n);
            float2 mhi = *(const float2*)(phi + n);
            float2 vlo = make_float2(c[i][j][0] + fb.x + mlo.x,
                                     c[i][j][1] + fb.y + mlo.y);
            float2 vhi = make_float2(c[i][j][2] + fb.x + mhi.x,
                                     c[i][j][3] + fb.y + mhi.y);
            *(float2*)(olo + n) = vlo;
            *(float2*)(ohi + n) = vhi;
        }
    }
}

// ---------------------------------------------------------------------------
// Kernel 4: in-place LayerNorm + sigmoid over rows of out_master
// ---------------------------------------------------------------------------
__global__ void ln_kernel(float* __restrict__ out_master,
                          const float* __restrict__ ln_g,
                          const float* __restrict__ ln_b)
{
    int b   = blockIdx.x;
    int tid = threadIdx.x;   // 256
    float* row = out_master + (size_t)b * HD;

    float v[8];
    float sum = 0.f, sq = 0.f;
    #pragma unroll
    for (int i = 0; i < 2; i++) {
        float4 t = *(const float4*)(row + tid * 4 + i * 1024);
        v[i * 4 + 0] = t.x; v[i * 4 + 1] = t.y; v[i * 4 + 2] = t.z; v[i * 4 + 3] = t.w;
        sum += t.x + t.y + t.z + t.w;
        sq  += t.x * t.x + t.y * t.y + t.z * t.z + t.w * t.w;
    }
    #pragma unroll
    for (int o = 16; o > 0; o >>= 1) {
        sum += __shfl_down_sync(0xffffffffu, sum, o);
        sq  += __shfl_down_sync(0xffffffffu, sq, o);
    }
    __shared__ float ssum[8], ssq[8];
    int wid = tid >> 5, lid = tid & 31;
    if (lid == 0) { ssum[wid] = sum; ssq[wid] = sq; }
    __syncthreads();
    __shared__ float s_mu, s_rstd;
    if (tid == 0) {
        float ts = 0.f, tq = 0.f;
        #pragma unroll
        for (int w = 0; w < 8; w++) { ts += ssum[w]; tq += ssq[w]; }
        float mu  = ts / (float)HD;
        float var = tq / (float)HD - mu * mu;
        s_mu = mu;
        s_rstd = rsqrtf(var + LN_EPS);
    }
    __syncthreads();
    float mu = s_mu, rstd = s_rstd;
    #pragma unroll
    for (int i = 0; i < 2; i++) {
        int h0 = tid * 4 + i * 1024;
        float4 o;
        float n0 = (v[i * 4 + 0] - mu) * rstd * ln_g[h0 + 0] + ln_b[h0 + 0];
        float n1 = (v[i * 4 + 1] - mu) * rstd * ln_g[h0 + 1] + ln_b[h0 + 1];
        float n2 = (v[i * 4 + 2] - mu) * rstd * ln_g[h0 + 2] + ln_b[h0 + 2];
        float n3 = (v[i * 4 + 3] - mu) * rstd * ln_g[h0 + 3] + ln_b[h0 + 3];
        o.x = 1.f / (1.f + expf(-n0));
        o.y = 1.f / (1.f + expf(-n1));
        o.z = 1.f / (1.f + expf(-n2));
        o.w = 1.f / (1.f + expf(-n3));
        *(float4*)(row + h0) = o;
    }
}

// ---------------------------------------------------------------------------
// Launch
// ---------------------------------------------------------------------------
extern "C" void kernel_launch(void* const* d_in, const int* in_sizes, int n_in,
                              void* d_out, int out_size)
{
    const float* x           = (const float*)d_in[0];   // [B, I]
    const float* prev_master = (const float*)d_in[1];   // [B, H]
    const float* prev_sub    = (const float*)d_in[2];   // [S, B, H]
    const float* gumbel      = (const float*)d_in[3];   // [B, S]
    const float* W_ih        = (const float*)d_in[4];   // [S, H, I]
    const float* W_hh        = (const float*)d_in[5];   // [S, H, H]
    const float* b_ih        = (const float*)d_in[6];   // [S, H]
    const float* b_hh        = (const float*)d_in[7];   // [S, H]
    const float* gate_W      = (const float*)d_in[8];   // [S, H]
    const float* gate_b      = (const float*)d_in[9];   // [S]
    const float* fusion_W    = (const float*)d_in[10];  // [H, H]
    const float* fusion_b    = (const float*)d_in[11];  // [H]
    const float* ln_g        = (const float*)d_in[12];  // [H]
    const float* ln_b        = (const float*)d_in[13];  // [H]

    float* out        = (float*)d_out;
    float* out_master = out;                                  // B*H
    float* out_gate   = out + (size_t)BSZ * HD;               // B*S
    float* out_sub    = out + (size_t)BSZ * HD + BSZ * NS;    // S*B*H

    cudaFuncSetAttribute(subcell_kernel,
                         cudaFuncAttributeMaxDynamicSharedMemorySize, SMEM_BYTES);
    cudaFuncSetAttribute(fusion_kernel,
                         cudaFuncAttributeMaxDynamicSharedMemorySize, SMEM_BYTES);

    gate_kernel<<<BSZ, 128>>>(prev_master, gumbel, gate_W, gate_b, out_gate);

    dim3 g2(HD / BN, BSZ / BM, NS);   // (16, 32, 3)
    subcell_kernel<<<g2, NTHREADS, SMEM_BYTES>>>(x, prev_sub, W_ih, W_hh,
                                                 b_ih, b_hh, out_sub);

    dim3 g3(HD / BN, BSZ / BM);       // (16, 32)
    fusion_kernel<<<g3, NTHREADS, SMEM_BYTES>>>(fusion_W, fusion_b,
                                                prev_master, out_master);

    ln_kernel<<<BSZ, 256>>>(out_master, ln_g, ln_b);
}

// round 4
// speedup vs baseline: 7.2990x; 1.9854x over previous
#include <cuda_runtime.h>
#include <cuda_fp16.h>
#include <math.h>
#include <stdint.h>

// Problem dims (fixed)
#define BSZ 4096
#define HD  2048
#define ID  2048
#define NS  3
#define LN_EPS 1e-5f

// GEMM tile config (fp16 mma.sync m16n8k16)
#define BM 128
#define BN 128
#define BK 64                    // f16 elems per K tile (128B rows)
#define NTHREADS 128
#define ROWB 144                 // padded row bytes (128 data + 16 pad)
#define STAGE_B (128 * ROWB)     // 18432 bytes per operand stage
#define SMEM_BYTES (4 * STAGE_B) // A0,A1,B0,B1 = 73728

// Scratch (static device globals; no dynamic alloc allowed)
__device__ __half g_x16[(size_t)BSZ * ID];
__device__ __half g_sub16[(size_t)NS * BSZ * HD];
__device__ __half g_wih16[(size_t)NS * HD * ID];
__device__ __half g_whh16[(size_t)NS * HD * HD];
__device__ __half g_fw16[(size_t)HD * HD];
__device__ __half g_weighted16[(size_t)BSZ * HD];
__device__ int    g_sel[BSZ];

// ---------------------------------------------------------------------------
// helpers
// ---------------------------------------------------------------------------
__device__ __forceinline__ uint32_t smem_u32(const void* p) {
    uint32_t a;
    asm("{ .reg .u64 t; cvta.to.shared.u64 t, %1; cvt.u32.u64 %0, t; }"
        : "=r"(a) : "l"(p));
    return a;
}
__device__ __forceinline__ void cp16(uint32_t dst, const void* src) {
    asm volatile("cp.async.cg.shared.global [%0], [%1], 16;"
                 :: "r"(dst), "l"(src) : "memory");
}
__device__ __forceinline__ void cp_commit() {
    asm volatile("cp.async.commit_group;" ::: "memory");
}
template <int N> __device__ __forceinline__ void cp_wait() {
    asm volatile("cp.async.wait_group %0;" :: "n"(N) : "memory");
}
__device__ __forceinline__ void ldsm_x4(uint32_t& r0, uint32_t& r1,
                                        uint32_t& r2, uint32_t& r3,
                                        uint32_t addr) {
    asm volatile("ldmatrix.sync.aligned.m8n8.x4.shared.b16 {%0,%1,%2,%3}, [%4];"
                 : "=r"(r0), "=r"(r1), "=r"(r2), "=r"(r3) : "r"(addr));
}
__device__ __forceinline__ void mma_f16(float c[4], uint32_t a0, uint32_t a1,
                                        uint32_t a2, uint32_t a3,
                                        uint32_t b0, uint32_t b1) {
    asm volatile(
        "mma.sync.aligned.m16n8k16.row.col.f32.f16.f16.f32 "
        "{%0,%1,%2,%3}, {%4,%5,%6,%7}, {%8,%9}, {%0,%1,%2,%3};"
        : "+f"(c[0]), "+f"(c[1]), "+f"(c[2]), "+f"(c[3])
        : "r"(a0), "r"(a1), "r"(a2), "r"(a3), "r"(b0), "r"(b1));
}

// ---------------------------------------------------------------------------
// Kernel 0: f32 -> f16 conversion (vectorized, grid-stride)
// ---------------------------------------------------------------------------
__global__ void cvt_f16_kernel(const float* __restrict__ in,
                               __half* __restrict__ out, size_t n)
{
    size_t i = ((size_t)blockIdx.x * blockDim.x + threadIdx.x) * 8;
    size_t stride = (size_t)gridDim.x * blockDim.x * 8;
    for (; i < n; i += stride) {
        float4 v0 = *(const float4*)(in + i);
        float4 v1 = *(const float4*)(in + i + 4);
        __half2 h0 = __floats2half2_rn(v0.x, v0.y);
        __half2 h1 = __floats2half2_rn(v0.z, v0.w);
        __half2 h2 = __floats2half2_rn(v1.x, v1.y);
        __half2 h3 = __floats2half2_rn(v1.z, v1.w);
        uint4 o;
        o.x = *(uint32_t*)&h0; o.y = *(uint32_t*)&h1;
        o.z = *(uint32_t*)&h2; o.w = *(uint32_t*)&h3;
        *(uint4*)(out + i) = o;
    }
}

// ---------------------------------------------------------------------------
// Kernel 1: gate logits + hard gumbel-softmax (numerically exact one-hot)
// ---------------------------------------------------------------------------
__global__ void gate_kernel(const float* __restrict__ prev_master,
                            const float* __restrict__ gumbel,
                            const float* __restrict__ gate_W,
                            const float* __restrict__ gate_b,
                            float* __restrict__ out_gate)
{
    int b   = blockIdx.x;
    int tid = threadIdx.x;   // 128 threads
    const float* row = prev_master + (size_t)b * HD;

    float p0 = 0.f, p1 = 0.f, p2 = 0.f;
    for (int h = tid * 4; h < HD; h += 128 * 4) {
        float4 v  = *(const float4*)(row + h);
        float4 w0 = *(const float4*)(gate_W + 0 * HD + h);
        float4 w1 = *(const float4*)(gate_W + 1 * HD + h);
        float4 w2 = *(const float4*)(gate_W + 2 * HD + h);
        p0 += v.x * w0.x + v.y * w0.y + v.z * w0.z + v.w * w0.w;
        p1 += v.x * w1.x + v.y * w1.y + v.z * w1.z + v.w * w1.w;
        p2 += v.x * w2.x + v.y * w2.y + v.z * w2.z + v.w * w2.w;
    }
    #pragma unroll
    for (int o = 16; o > 0; o >>= 1) {
        p0 += __shfl_down_sync(0xffffffffu, p0, o);
        p1 += __shfl_down_sync(0xffffffffu, p1, o);
        p2 += __shfl_down_sync(0xffffffffu, p2, o);
    }
    __shared__ float s0[4], s1[4], s2[4];
    int wid = tid >> 5, lid = tid & 31;
    if (lid == 0) { s0[wid] = p0; s1[wid] = p1; s2[wid] = p2; }
    __syncthreads();
    if (tid == 0) {
        float z0 = s0[0] + s0[1] + s0[2] + s0[3] + gate_b[0] + gumbel[b * 3 + 0];
        float z1 = s1[0] + s1[1] + s1[2] + s1[3] + gate_b[1] + gumbel[b * 3 + 1];
        float z2 = s2[0] + s2[1] + s2[2] + s2[3] + gate_b[2] + gumbel[b * 3 + 2];
        int am = 0; float zm = z0;
        if (z1 > zm) { am = 1; zm = z1; }
        if (z2 > zm) { am = 2; }
        out_gate[b * 3 + 0] = (am == 0) ? 1.f : 0.f;
        out_gate[b * 3 + 1] = (am == 1) ? 1.f : 0.f;
        out_gate[b * 3 + 2] = (am == 2) ? 1.f : 0.f;
        g_sel[b] = am;
    }
}

// ---------------------------------------------------------------------------
// fp16 mma.sync GEMM core.  C[128,128] per CTA, 4 warps 2x2, warp tile 64x64.
// A: [.,2048] f16 row-major; W: [.,2048] f16 row-major (acts as col-major B).
// ---------------------------------------------------------------------------
struct GemmCtx {
    uint32_t sm32;
    int tid, lane, g, tg, wm0, wn0;
};

__device__ __forceinline__ void gemm_init(GemmCtx& cx, void* sm) {
    cx.sm32 = smem_u32(sm);
    cx.tid  = threadIdx.x;
    cx.lane = cx.tid & 31;
    cx.g    = cx.lane >> 2;
    cx.tg   = cx.lane & 3;
    int wid = cx.tid >> 5;
    cx.wm0  = (wid >> 1) * 64;
    cx.wn0  = (wid & 1) * 64;
}

// load one BK=64 tile of A (rows m0..+127) and B (rows n0..+127) into stage sl
__device__ __forceinline__ void gemm_load(const GemmCtx& cx,
                                          const __half* __restrict__ A, int m0,
                                          const __half* __restrict__ Bw, int n0,
                                          int kc, int sl) {
    int r0  = cx.tid >> 3;         // 0..15
    int seg = cx.tid & 7;          // 16B segment in row
    uint32_t abase = cx.sm32 + sl * STAGE_B;
    uint32_t bbase = cx.sm32 + 2 * STAGE_B + sl * STAGE_B;
    #pragma unroll
    for (int p = 0; p < 8; p++) {
        int r = r0 + p * 16;
        cp16(abase + r * ROWB + seg * 16, A  + (size_t)(m0 + r) * 2048 + kc + seg * 8);
        cp16(bbase + r * ROWB + seg * 16, Bw + (size_t)(n0 + r) * 2048 + kc + seg * 8);
    }
}

__device__ __forceinline__ void gemm_compute(const GemmCtx& cx, int sl,
                                             float c[4][8][4]) {
    uint32_t As = cx.sm32 + sl * STAGE_B;
    uint32_t Bs = cx.sm32 + 2 * STAGE_B + sl * STAGE_B;
    int l = cx.lane;
    // ldmatrix address components
    int arow = cx.wm0 + (l & 15);
    int aks  = (l >> 4) * 8;                        // 0 or 8
    int brow0 = cx.wn0 + (l & 7) + ((l >> 4) << 3); // n row
    int bks  = ((l >> 3) & 1) * 8;
    #pragma unroll
    for (int kk = 0; kk < BK; kk += 16) {
        uint32_t a[4][4], b[8][2];
        #pragma unroll
        for (int i = 0; i < 4; i++) {
            ldsm_x4(a[i][0], a[i][1], a[i][2], a[i][3],
                    As + (arow + i * 16) * ROWB + (kk + aks) * 2);
        }
        #pragma unroll
        for (int j2 = 0; j2 < 4; j2++) {
            ldsm_x4(b[j2 * 2][0], b[j2 * 2][1], b[j2 * 2 + 1][0], b[j2 * 2 + 1][1],
                    Bs + (brow0 + j2 * 16) * ROWB + (kk + bks) * 2);
        }
        #pragma unroll
        for (int i = 0; i < 4; i++)
            #pragma unroll
            for (int j = 0; j < 8; j++)
                mma_f16(c[i][j], a[i][0], a[i][1], a[i][2], a[i][3],
                        b[j][0], b[j][1]);
    }
}

// ---------------------------------------------------------------------------
// Kernel 2: sub-cell RNN.  K = 4096 total (x@W_ih^T then h@W_hh^T), tanh epi.
// ---------------------------------------------------------------------------
__global__ __launch_bounds__(NTHREADS, 2)
void subcell_kernel(const float* __restrict__ b_ih,
                    const float* __restrict__ b_hh,
                    float* __restrict__ out_sub)
{
    extern __shared__ char smraw[];
    GemmCtx cx; gemm_init(cx, smraw);
    const int s  = blockIdx.z;
    const int m0 = blockIdx.y * BM;
    const int n0 = blockIdx.x * BN;

    const __half* A0 = g_x16;
    const __half* A1 = g_sub16 + (size_t)s * BSZ * HD;
    const __half* B0 = g_wih16 + (size_t)s * HD * ID;
    const __half* B1 = g_whh16 + (size_t)s * HD * HD;

    float c[4][8][4];
    #pragma unroll
    for (int i = 0; i < 4; i++)
        #pragma unroll
        for (int j = 0; j < 8; j++)
            #pragma unroll
            for (int q = 0; q < 4; q++) c[i][j][q] = 0.f;

    const int NT = 64;  // 32 tiles (x,W_ih) + 32 tiles (h,W_hh)
    auto tile_load = [&](int t, int sl) {
        if (t < 32) gemm_load(cx, A0, m0, B0, n0, t * BK, sl);
        else        gemm_load(cx, A1, m0, B1, n0, (t - 32) * BK, sl);
    };

    tile_load(0, 0); cp_commit();
    tile_load(1, 1); cp_commit();

    for (int t = 0; t < NT; t++) {
        cp_wait<1>();
        __syncthreads();
        gemm_compute(cx, t & 1, c);
        __syncthreads();
        if (t + 2 < NT) tile_load(t + 2, t & 1);
        cp_commit();
    }

    // epilogue: bias + tanh -> out_sub (f32); conditional gather -> weighted16
    const float* bi = b_ih + (size_t)s * HD;
    const float* bh = b_hh + (size_t)s * HD;
    #pragma unroll
    for (int i = 0; i < 4; i++) {
        int rlo = m0 + cx.wm0 + i * 16 + cx.g;
        int rhi = rlo + 8;
        int selo = g_sel[rlo], sehi = g_sel[rhi];
        float* olo = out_sub + ((size_t)s * BSZ + rlo) * HD;
        float* ohi = out_sub + ((size_t)s * BSZ + rhi) * HD;
        __half* wlo = g_weighted16 + (size_t)rlo * HD;
        __half* whi = g_weighted16 + (size_t)rhi * HD;
        #pragma unroll
        for (int j = 0; j < 8; j++) {
            int n = n0 + cx.wn0 + j * 8 + cx.tg * 2;
            float2 bv0 = *(const float2*)(bi + n);
            float2 bv1 = *(const float2*)(bh + n);
            float bs0 = bv0.x + bv1.x, bs1 = bv0.y + bv1.y;
            float2 vlo = make_float2(tanhf(c[i][j][0] + bs0),
                                     tanhf(c[i][j][1] + bs1));
            float2 vhi = make_float2(tanhf(c[i][j][2] + bs0),
                                     tanhf(c[i][j][3] + bs1));
            *(float2*)(olo + n) = vlo;
            *(float2*)(ohi + n) = vhi;
            if (selo == s) *(__half2*)(wlo + n) = __floats2half2_rn(vlo.x, vlo.y);
            if (sehi == s) *(__half2*)(whi + n) = __floats2half2_rn(vhi.x, vhi.y);
        }
    }
}

// ---------------------------------------------------------------------------
// Kernel 3: fusion GEMM.  pre = prev_master + weighted @ fusion_W^T + fusion_b
// ---------------------------------------------------------------------------
__global__ __launch_bounds__(NTHREADS, 2)
void fusion_kernel(const float* __restrict__ fusion_b,
                   const float* __restrict__ prev_master,
                   float* __restrict__ out_master)
{
    extern __shared__ char smraw[];
    GemmCtx cx; gemm_init(cx, smraw);
    const int m0 = blockIdx.y * BM;
    const int n0 = blockIdx.x * BN;

    float c[4][8][4];
    #pragma unroll
    for (int i = 0; i < 4; i++)
        #pragma unroll
        for (int j = 0; j < 8; j++)
            #pragma unroll
            for (int q = 0; q < 4; q++) c[i][j][q] = 0.f;

    const int NT = 32;
    gemm_load(cx, g_weighted16, m0, g_fw16, n0, 0, 0);   cp_commit();
    gemm_load(cx, g_weighted16, m0, g_fw16, n0, BK, 1);  cp_commit();

    for (int t = 0; t < NT; t++) {
        cp_wait<1>();
        __syncthreads();
        gemm_compute(cx, t & 1, c);
        __syncthreads();
        if (t + 2 < NT) gemm_load(cx, g_weighted16, m0, g_fw16, n0, (t + 2) * BK, t & 1);
        cp_commit();
    }

    // epilogue: + fusion_b + prev_master (pre-LN values)
    #pragma unroll
    for (int i = 0; i < 4; i++) {
        int rlo = m0 + cx.wm0 + i * 16 + cx.g;
        int rhi = rlo + 8;
        const float* plo = prev_master + (size_t)rlo * HD;
        const float* phi = prev_master + (size_t)rhi * HD;
        float* olo = out_master + (size_t)rlo * HD;
        float* ohi = out_master + (size_t)rhi * HD;
        #pragma unroll
        for (int j = 0; j < 8; j++) {
            int n = n0 + cx.wn0 + j * 8 + cx.tg * 2;
            float2 fb = *(const float2*)(fusion_b + n);
            float2 mlo = *(const float2*)(plo + n);
            float2 mhi = *(const float2*)(phi + n);
            float2 vlo = make_float2(c[i][j][0] + fb.x + mlo.x,
                                     c[i][j][1] + fb.y + mlo.y);
            float2 vhi = make_float2(c[i][j][2] + fb.x + mhi.x,
                                     c[i][j][3] + fb.y + mhi.y);
            *(float2*)(olo + n) = vlo;
            *(float2*)(ohi + n) = vhi;
        }
    }
}

// ---------------------------------------------------------------------------
// Kernel 4: in-place LayerNorm + sigmoid over rows of out_master
// ---------------------------------------------------------------------------
__global__ void ln_kernel(float* __restrict__ out_master,
                          const float* __restrict__ ln_g,
                          const float* __restrict__ ln_b)
{
    int b   = blockIdx.x;
    int tid = threadIdx.x;   // 256
    float* row = out_master + (size_t)b * HD;

    float v[8];
    float sum = 0.f, sq = 0.f;
    #pragma unroll
    for (int i = 0; i < 2; i++) {
        float4 t = *(const float4*)(row + tid * 4 + i * 1024);
        v[i * 4 + 0] = t.x; v[i * 4 + 1] = t.y; v[i * 4 + 2] = t.z; v[i * 4 + 3] = t.w;
        sum += t.x + t.y + t.z + t.w;
        sq  += t.x * t.x + t.y * t.y + t.z * t.z + t.w * t.w;
    }
    #pragma unroll
    for (int o = 16; o > 0; o >>= 1) {
        sum += __shfl_down_sync(0xffffffffu, sum, o);
        sq  += __shfl_down_sync(0xffffffffu, sq, o);
    }
    __shared__ float ssum[8], ssq[8];
    int wid = tid >> 5, lid = tid & 31;
    if (lid == 0) { ssum[wid] = sum; ssq[wid] = sq; }
    __syncthreads();
    __shared__ float s_mu, s_rstd;
    if (tid == 0) {
        float ts = 0.f, tq = 0.f;
        #pragma unroll
        for (int w = 0; w < 8; w++) { ts += ssum[w]; tq += ssq[w]; }
        float mu  = ts / (float)HD;
        float var = tq / (float)HD - mu * mu;
        s_mu = mu;
        s_rstd = rsqrtf(var + LN_EPS);
    }
    __syncthreads();
    float mu = s_mu, rstd = s_rstd;
    #pragma unroll
    for (int i = 0; i < 2; i++) {
        int h0 = tid * 4 + i * 1024;
        float4 o;
        float n0 = (v[i * 4 + 0] - mu) * rstd * ln_g[h0 + 0] + ln_b[h0 + 0];
        float n1 = (v[i * 4 + 1] - mu) * rstd * ln_g[h0 + 1] + ln_b[h0 + 1];
        float n2 = (v[i * 4 + 2] - mu) * rstd * ln_g[h0 + 2] + ln_b[h0 + 2];
        float n3 = (v[i * 4 + 3] - mu) * rstd * ln_g[h0 + 3] + ln_b[h0 + 3];
        o.x = 1.f / (1.f + expf(-n0));
        o.y = 1.f / (1.f + expf(-n1));
        o.z = 1.f / (1.f + expf(-n2));
        o.w = 1.f / (1.f + expf(-n3));
        *(float4*)(row + h0) = o;
    }
}

// ---------------------------------------------------------------------------
// Launch
// ---------------------------------------------------------------------------
extern "C" void kernel_launch(void* const* d_in, const int* in_sizes, int n_in,
                              void* d_out, int out_size)
{
    const float* x           = (const float*)d_in[0];   // [B, I]
    const float* prev_master = (const float*)d_in[1];   // [B, H]
    const float* prev_sub    = (const float*)d_in[2];   // [S, B, H]
    const float* gumbel      = (const float*)d_in[3];   // [B, S]
    const float* W_ih        = (const float*)d_in[4];   // [S, H, I]
    const float* W_hh        = (const float*)d_in[5];   // [S, H, H]
    const float* b_ih        = (const float*)d_in[6];   // [S, H]
    const float* b_hh        = (const float*)d_in[7];   // [S, H]
    const float* gate_W      = (const float*)d_in[8];   // [S, H]
    const float* gate_b      = (const float*)d_in[9];   // [S]
    const float* fusion_W    = (const float*)d_in[10];  // [H, H]
    const float* fusion_b    = (const float*)d_in[11];  // [H]
    const float* ln_g        = (const float*)d_in[12];  // [H]
    const float* ln_b        = (const float*)d_in[13];  // [H]

    float* out        = (float*)d_out;
    float* out_master = out;                                  // B*H
    float* out_gate   = out + (size_t)BSZ * HD;               // B*S
    float* out_sub    = out + (size_t)BSZ * HD + BSZ * NS;    // S*B*H

    cudaFuncSetAttribute(subcell_kernel,
                         cudaFuncAttributeMaxDynamicSharedMemorySize, SMEM_BYTES);
    cudaFuncSetAttribute(fusion_kernel,
                         cudaFuncAttributeMaxDynamicSharedMemorySize, SMEM_BYTES);

    // f32 -> f16 conversion of GEMM operands
    __half *p_x16, *p_sub16, *p_wih16, *p_whh16, *p_fw16;
    cudaGetSymbolAddress((void**)&p_x16,   g_x16);
    cudaGetSymbolAddress((void**)&p_sub16, g_sub16);
    cudaGetSymbolAddress((void**)&p_wih16, g_wih16);
    cudaGetSymbolAddress((void**)&p_whh16, g_whh16);
    cudaGetSymbolAddress((void**)&p_fw16,  g_fw16);

    cvt_f16_kernel<<<1184, 256>>>(x,        p_x16,   (size_t)BSZ * ID);
    cvt_f16_kernel<<<1184, 256>>>(prev_sub, p_sub16, (size_t)NS * BSZ * HD);
    cvt_f16_kernel<<<1184, 256>>>(W_ih,     p_wih16, (size_t)NS * HD * ID);
    cvt_f16_kernel<<<1184, 256>>>(W_hh,     p_whh16, (size_t)NS * HD * HD);
    cvt_f16_kernel<<<1184, 256>>>(fusion_W, p_fw16,  (size_t)HD * HD);

    gate_kernel<<<BSZ, 128>>>(prev_master, gumbel, gate_W, gate_b, out_gate);

    dim3 g2(HD / BN, BSZ / BM, NS);   // (16, 32, 3)
    subcell_kernel<<<g2, NTHREADS, SMEM_BYTES>>>(b_ih, b_hh, out_sub);

    dim3 g3(HD / BN, BSZ / BM);       // (16, 32)
    fusion_kernel<<<g3, NTHREADS, SMEM_BYTES>>>(fusion_b, prev_master, out_master);

    ln_kernel<<<BSZ, 256>>>(out_master, ln_g, ln_b);
}

// round 5
// speedup vs baseline: 7.4853x; 1.0255x over previous
#include <cuda_runtime.h>
#include <cuda_fp16.h>
#include <math.h>
#include <stdint.h>

// Problem dims (fixed)
#define BSZ 4096
#define HD  2048
#define ID  2048
#define NS  3
#define LN_EPS 1e-5f

// GEMM tile config (fp16 mma.sync m16n8k16)
#define BM 128
#define BN 128
#define BK 64                    // f16 elems per K tile (128B rows)
#define NTHREADS 128
#define NSTAGE 3
#define ROWB 144                 // padded row bytes (128 data + 16 pad)
#define STAGE_B (128 * ROWB)     // 18432 bytes per operand stage
#define SMEM_BYTES (NSTAGE * 2 * STAGE_B)  // 110592

// Scratch (static device globals; no dynamic alloc allowed)
__device__ __half g_x16[(size_t)BSZ * ID];
__device__ __half g_sub16[(size_t)NS * BSZ * HD];
__device__ __half g_wih16[(size_t)NS * HD * ID];
__device__ __half g_whh16[(size_t)NS * HD * HD];
__device__ __half g_fw16[(size_t)HD * HD];
__device__ __half g_weighted16[(size_t)BSZ * HD];
__device__ int    g_sel[BSZ];

// ---------------------------------------------------------------------------
// helpers
// ---------------------------------------------------------------------------
__device__ __forceinline__ uint32_t smem_u32(const void* p) {
    uint32_t a;
    asm("{ .reg .u64 t; cvta.to.shared.u64 t, %1; cvt.u32.u64 %0, t; }"
        : "=r"(a) : "l"(p));
    return a;
}
__device__ __forceinline__ void cp16(uint32_t dst, const void* src) {
    asm volatile("cp.async.cg.shared.global [%0], [%1], 16;"
                 :: "r"(dst), "l"(src) : "memory");
}
__device__ __forceinline__ void cp_commit() {
    asm volatile("cp.async.commit_group;" ::: "memory");
}
template <int N> __device__ __forceinline__ void cp_wait() {
    asm volatile("cp.async.wait_group %0;" :: "n"(N) : "memory");
}
__device__ __forceinline__ void ldsm_x4(uint32_t& r0, uint32_t& r1,
                                        uint32_t& r2, uint32_t& r3,
                                        uint32_t addr) {
    asm volatile("ldmatrix.sync.aligned.m8n8.x4.shared.b16 {%0,%1,%2,%3}, [%4];"
                 : "=r"(r0), "=r"(r1), "=r"(r2), "=r"(r3) : "r"(addr));
}
__device__ __forceinline__ void mma_f16(float c[4], uint32_t a0, uint32_t a1,
                                        uint32_t a2, uint32_t a3,
                                        uint32_t b0, uint32_t b1) {
    asm volatile(
        "mma.sync.aligned.m16n8k16.row.col.f32.f16.f16.f32 "
        "{%0,%1,%2,%3}, {%4,%5,%6,%7}, {%8,%9}, {%0,%1,%2,%3};"
        : "+f"(c[0]), "+f"(c[1]), "+f"(c[2]), "+f"(c[3])
        : "r"(a0), "r"(a1), "r"(a2), "r"(a3), "r"(b0), "r"(b1));
}

// ---------------------------------------------------------------------------
// Kernel 0: f32 -> f16 conversion (vectorized, 16 elems/thread/iter)
// ---------------------------------------------------------------------------
__global__ void cvt_f16_kernel(const float* __restrict__ in,
                               __half* __restrict__ out, size_t n)
{
    size_t i = ((size_t)blockIdx.x * blockDim.x + threadIdx.x) * 16;
    size_t stride = (size_t)gridDim.x * blockDim.x * 16;
    for (; i < n; i += stride) {
        float4 v0 = *(const float4*)(in + i);
        float4 v1 = *(const float4*)(in + i + 4);
        float4 v2 = *(const float4*)(in + i + 8);
        float4 v3 = *(const float4*)(in + i + 12);
        __half2 h0 = __floats2half2_rn(v0.x, v0.y);
        __half2 h1 = __floats2half2_rn(v0.z, v0.w);
        __half2 h2 = __floats2half2_rn(v1.x, v1.y);
        __half2 h3 = __floats2half2_rn(v1.z, v1.w);
        __half2 h4 = __floats2half2_rn(v2.x, v2.y);
        __half2 h5 = __floats2half2_rn(v2.z, v2.w);
        __half2 h6 = __floats2half2_rn(v3.x, v3.y);
        __half2 h7 = __floats2half2_rn(v3.z, v3.w);
        uint4 o0, o1;
        o0.x = *(uint32_t*)&h0; o0.y = *(uint32_t*)&h1;
        o0.z = *(uint32_t*)&h2; o0.w = *(uint32_t*)&h3;
        o1.x = *(uint32_t*)&h4; o1.y = *(uint32_t*)&h5;
        o1.z = *(uint32_t*)&h6; o1.w = *(uint32_t*)&h7;
        *(uint4*)(out + i)     = o0;
        *(uint4*)(out + i + 8) = o1;
    }
}

// ---------------------------------------------------------------------------
// Kernel 1: gate logits + hard gumbel-softmax (numerically exact one-hot)
// ---------------------------------------------------------------------------
__global__ void gate_kernel(const float* __restrict__ prev_master,
                            const float* __restrict__ gumbel,
                            const float* __restrict__ gate_W,
                            const float* __restrict__ gate_b,
                            float* __restrict__ out_gate)
{
    int b   = blockIdx.x;
    int tid = threadIdx.x;   // 128 threads
    const float* row = prev_master + (size_t)b * HD;

    float p0 = 0.f, p1 = 0.f, p2 = 0.f;
    for (int h = tid * 4; h < HD; h += 128 * 4) {
        float4 v  = *(const float4*)(row + h);
        float4 w0 = *(const float4*)(gate_W + 0 * HD + h);
        float4 w1 = *(const float4*)(gate_W + 1 * HD + h);
        float4 w2 = *(const float4*)(gate_W + 2 * HD + h);
        p0 += v.x * w0.x + v.y * w0.y + v.z * w0.z + v.w * w0.w;
        p1 += v.x * w1.x + v.y * w1.y + v.z * w1.z + v.w * w1.w;
        p2 += v.x * w2.x + v.y * w2.y + v.z * w2.z + v.w * w2.w;
    }
    #pragma unroll
    for (int o = 16; o > 0; o >>= 1) {
        p0 += __shfl_down_sync(0xffffffffu, p0, o);
        p1 += __shfl_down_sync(0xffffffffu, p1, o);
        p2 += __shfl_down_sync(0xffffffffu, p2, o);
    }
    __shared__ float s0[4], s1[4], s2[4];
    int wid = tid >> 5, lid = tid & 31;
    if (lid == 0) { s0[wid] = p0; s1[wid] = p1; s2[wid] = p2; }
    __syncthreads();
    if (tid == 0) {
        float z0 = s0[0] + s0[1] + s0[2] + s0[3] + gate_b[0] + gumbel[b * 3 + 0];
        float z1 = s1[0] + s1[1] + s1[2] + s1[3] + gate_b[1] + gumbel[b * 3 + 1];
        float z2 = s2[0] + s2[1] + s2[2] + s2[3] + gate_b[2] + gumbel[b * 3 + 2];
        int am = 0; float zm = z0;
        if (z1 > zm) { am = 1; zm = z1; }
        if (z2 > zm) { am = 2; }
        out_gate[b * 3 + 0] = (am == 0) ? 1.f : 0.f;
        out_gate[b * 3 + 1] = (am == 1) ? 1.f : 0.f;
        out_gate[b * 3 + 2] = (am == 2) ? 1.f : 0.f;
        g_sel[b] = am;
    }
}

// ---------------------------------------------------------------------------
// fp16 mma.sync GEMM core.  C[128,128] per CTA, 4 warps 2x2, warp tile 64x64.
// 3-stage cp.async pipeline, one __syncthreads per K tile.
// ---------------------------------------------------------------------------
struct GemmCtx {
    uint32_t sm32;
    int tid, lane, g, tg, wm0, wn0;
};

__device__ __forceinline__ void gemm_init(GemmCtx& cx, void* sm) {
    cx.sm32 = smem_u32(sm);
    cx.tid  = threadIdx.x;
    cx.lane = cx.tid & 31;
    cx.g    = cx.lane >> 2;
    cx.tg   = cx.lane & 3;
    int wid = cx.tid >> 5;
    cx.wm0  = (wid >> 1) * 64;
    cx.wn0  = (wid & 1) * 64;
}

// load one BK=64 tile of A (rows m0..+127) and B (rows n0..+127) into stage sl
__device__ __forceinline__ void gemm_load(const GemmCtx& cx,
                                          const __half* __restrict__ A, int m0,
                                          const __half* __restrict__ Bw, int n0,
                                          int kc, int sl) {
    int r0  = cx.tid >> 3;         // 0..15
    int seg = cx.tid & 7;          // 16B segment in row
    uint32_t abase = cx.sm32 + sl * (2 * STAGE_B);
    uint32_t bbase = abase + STAGE_B;
    #pragma unroll
    for (int p = 0; p < 8; p++) {
        int r = r0 + p * 16;
        cp16(abase + r * ROWB + seg * 16, A  + (size_t)(m0 + r) * 2048 + kc + seg * 8);
        cp16(bbase + r * ROWB + seg * 16, Bw + (size_t)(n0 + r) * 2048 + kc + seg * 8);
    }
}

__device__ __forceinline__ void gemm_compute(const GemmCtx& cx, int sl,
                                             float c[4][8][4]) {
    uint32_t As = cx.sm32 + sl * (2 * STAGE_B);
    uint32_t Bs = As + STAGE_B;
    int l = cx.lane;
    int arow = cx.wm0 + (l & 15);
    int aks  = (l >> 4) * 8;                        // 0 or 8
    int brow0 = cx.wn0 + (l & 7) + ((l >> 4) << 3); // n row
    int bks  = ((l >> 3) & 1) * 8;
    #pragma unroll
    for (int kk = 0; kk < BK; kk += 16) {
        uint32_t a[4][4], b[8][2];
        #pragma unroll
        for (int i = 0; i < 4; i++) {
            ldsm_x4(a[i][0], a[i][1], a[i][2], a[i][3],
                    As + (arow + i * 16) * ROWB + (kk + aks) * 2);
        }
        #pragma unroll
        for (int j2 = 0; j2 < 4; j2++) {
            ldsm_x4(b[j2 * 2][0], b[j2 * 2][1], b[j2 * 2 + 1][0], b[j2 * 2 + 1][1],
                    Bs + (brow0 + j2 * 16) * ROWB + (kk + bks) * 2);
        }
        #pragma unroll
        for (int i = 0; i < 4; i++)
            #pragma unroll
            for (int j = 0; j < 8; j++)
                mma_f16(c[i][j], a[i][0], a[i][1], a[i][2], a[i][3],
                        b[j][0], b[j][1]);
    }
}

// ---------------------------------------------------------------------------
// Kernel 2: sub-cell RNN.  K = 4096 total (x@W_ih^T then h@W_hh^T), tanh epi.
// ---------------------------------------------------------------------------
__global__ __launch_bounds__(NTHREADS, 2)
void subcell_kernel(const float* __restrict__ b_ih,
                    const float* __restrict__ b_hh,
                    float* __restrict__ out_sub)
{
    extern __shared__ char smraw[];
    GemmCtx cx; gemm_init(cx, smraw);
    const int s  = blockIdx.z;
    const int m0 = blockIdx.y * BM;
    const int n0 = blockIdx.x * BN;

    const __half* A0 = g_x16;
    const __half* A1 = g_sub16 + (size_t)s * BSZ * HD;
    const __half* B0 = g_wih16 + (size_t)s * HD * ID;
    const __half* B1 = g_whh16 + (size_t)s * HD * HD;

    float c[4][8][4];
    #pragma unroll
    for (int i = 0; i < 4; i++)
        #pragma unroll
        for (int j = 0; j < 8; j++)
            #pragma unroll
            for (int q = 0; q < 4; q++) c[i][j][q] = 0.f;

    const int NT = 64;  // 32 tiles (x,W_ih) + 32 tiles (h,W_hh)
    auto tile_load = [&](int t, int sl) {
        if (t < 32) gemm_load(cx, A0, m0, B0, n0, t * BK, sl);
        else        gemm_load(cx, A1, m0, B1, n0, (t - 32) * BK, sl);
    };

    // prefetch NSTAGE-1 tiles
    tile_load(0, 0); cp_commit();
    tile_load(1, 1); cp_commit();

    for (int t = 0; t < NT; t++) {
        cp_wait<NSTAGE - 2>();
        __syncthreads();
        int nt = t + NSTAGE - 1;
        if (nt < NT) tile_load(nt, nt % NSTAGE);
        cp_commit();
        gemm_compute(cx, t % NSTAGE, c);
    }

    // epilogue: bias + tanh -> out_sub (f32); conditional gather -> weighted16
    const float* bi = b_ih + (size_t)s * HD;
    const float* bh = b_hh + (size_t)s * HD;
    #pragma unroll
    for (int i = 0; i < 4; i++) {
        int rlo = m0 + cx.wm0 + i * 16 + cx.g;
        int rhi = rlo + 8;
        int selo = g_sel[rlo], sehi = g_sel[rhi];
        float* olo = out_sub + ((size_t)s * BSZ + rlo) * HD;
        float* ohi = out_sub + ((size_t)s * BSZ + rhi) * HD;
        __half* wlo = g_weighted16 + (size_t)rlo * HD;
        __half* whi = g_weighted16 + (size_t)rhi * HD;
        #pragma unroll
        for (int j = 0; j < 8; j++) {
            int n = n0 + cx.wn0 + j * 8 + cx.tg * 2;
            float2 bv0 = *(const float2*)(bi + n);
            float2 bv1 = *(const float2*)(bh + n);
            float bs0 = bv0.x + bv1.x, bs1 = bv0.y + bv1.y;
            float2 vlo = make_float2(tanhf(c[i][j][0] + bs0),
                                     tanhf(c[i][j][1] + bs1));
            float2 vhi = make_float2(tanhf(c[i][j][2] + bs0),
                                     tanhf(c[i][j][3] + bs1));
            *(float2*)(olo + n) = vlo;
            *(float2*)(ohi + n) = vhi;
            if (selo == s) *(__half2*)(wlo + n) = __floats2half2_rn(vlo.x, vlo.y);
            if (sehi == s) *(__half2*)(whi + n) = __floats2half2_rn(vhi.x, vhi.y);
        }
    }
}

// ---------------------------------------------------------------------------
// Kernel 3: fusion GEMM.  pre = prev_master + weighted @ fusion_W^T + fusion_b
// ---------------------------------------------------------------------------
__global__ __launch_bounds__(NTHREADS, 2)
void fusion_kernel(const float* __restrict__ fusion_b,
                   const float* __restrict__ prev_master,
                   float* __restrict__ out_master)
{
    extern __shared__ char smraw[];
    GemmCtx cx; gemm_init(cx, smraw);
    const int m0 = blockIdx.y * BM;
    const int n0 = blockIdx.x * BN;

    float c[4][8][4];
    #pragma unroll
    for (int i = 0; i < 4; i++)
        #pragma unroll
        for (int j = 0; j < 8; j++)
            #pragma unroll
            for (int q = 0; q < 4; q++) c[i][j][q] = 0.f;

    const int NT = 32;
    gemm_load(cx, g_weighted16, m0, g_fw16, n0, 0, 0);   cp_commit();
    gemm_load(cx, g_weighted16, m0, g_fw16, n0, BK, 1);  cp_commit();

    for (int t = 0; t < NT; t++) {
        cp_wait<NSTAGE - 2>();
        __syncthreads();
        int nt = t + NSTAGE - 1;
        if (nt < NT) gemm_load(cx, g_weighted16, m0, g_fw16, n0, nt * BK, nt % NSTAGE);
        cp_commit();
        gemm_compute(cx, t % NSTAGE, c);
    }

    // epilogue: + fusion_b + prev_master (pre-LN values)
    #pragma unroll
    for (int i = 0; i < 4; i++) {
        int rlo = m0 + cx.wm0 + i * 16 + cx.g;
        int rhi = rlo + 8;
        const float* plo = prev_master + (size_t)rlo * HD;
        const float* phi = prev_master + (size_t)rhi * HD;
        float* olo = out_master + (size_t)rlo * HD;
        float* ohi = out_master + (size_t)rhi * HD;
        #pragma unroll
        for (int j = 0; j < 8; j++) {
            int n = n0 + cx.wn0 + j * 8 + cx.tg * 2;
            float2 fb = *(const float2*)(fusion_b + n);
            float2 mlo = *(const float2*)(plo + n);
            float2 mhi = *(const float2*)(phi + n);
            float2 vlo = make_float2(c[i][j][0] + fb.x + mlo.x,
                                     c[i][j][1] + fb.y + mlo.y);
            float2 vhi = make_float2(c[i][j][2] + fb.x + mhi.x,
                                     c[i][j][3] + fb.y + mhi.y);
            *(float2*)(olo + n) = vlo;
            *(float2*)(ohi + n) = vhi;
        }
    }
}

// ---------------------------------------------------------------------------
// Kernel 4: in-place LayerNorm + sigmoid over rows of out_master
// ---------------------------------------------------------------------------
__global__ void ln_kernel(float* __restrict__ out_master,
                          const float* __restrict__ ln_g,
                          const float* __restrict__ ln_b)
{
    int b   = blockIdx.x;
    int tid = threadIdx.x;   // 256
    float* row = out_master + (size_t)b * HD;

    float v[8];
    float sum = 0.f, sq = 0.f;
    #pragma unroll
    for (int i = 0; i < 2; i++) {
        float4 t = *(const float4*)(row + tid * 4 + i * 1024);
        v[i * 4 + 0] = t.x; v[i * 4 + 1] = t.y; v[i * 4 + 2] = t.z; v[i * 4 + 3] = t.w;
        sum += t.x + t.y + t.z + t.w;
        sq  += t.x * t.x + t.y * t.y + t.z * t.z + t.w * t.w;
    }
    #pragma unroll
    for (int o = 16; o > 0; o >>= 1) {
        sum += __shfl_down_sync(0xffffffffu, sum, o);
        sq  += __shfl_down_sync(0xffffffffu, sq, o);
    }
    __shared__ float ssum[8], ssq[8];
    int wid = tid >> 5, lid = tid & 31;
    if (lid == 0) { ssum[wid] = sum; ssq[wid] = sq; }
    __syncthreads();
    __shared__ float s_mu, s_rstd;
    if (tid == 0) {
        float ts = 0.f, tq = 0.f;
        #pragma unroll
        for (int w = 0; w < 8; w++) { ts += ssum[w]; tq += ssq[w]; }
        float mu  = ts / (float)HD;
        float var = tq / (float)HD - mu * mu;
        s_mu = mu;
        s_rstd = rsqrtf(var + LN_EPS);
    }
    __syncthreads();
    float mu = s_mu, rstd = s_rstd;
    #pragma unroll
    for (int i = 0; i < 2; i++) {
        int h0 = tid * 4 + i * 1024;
        float4 o;
        float n0 = (v[i * 4 + 0] - mu) * rstd * ln_g[h0 + 0] + ln_b[h0 + 0];
        float n1 = (v[i * 4 + 1] - mu) * rstd * ln_g[h0 + 1] + ln_b[h0 + 1];
        float n2 = (v[i * 4 + 2] - mu) * rstd * ln_g[h0 + 2] + ln_b[h0 + 2];
        float n3 = (v[i * 4 + 3] - mu) * rstd * ln_g[h0 + 3] + ln_b[h0 + 3];
        o.x = 1.f / (1.f + expf(-n0));
        o.y = 1.f / (1.f + expf(-n1));
        o.z = 1.f / (1.f + expf(-n2));
        o.w = 1.f / (1.f + expf(-n3));
        *(float4*)(row + h0) = o;
    }
}

// ---------------------------------------------------------------------------
// Launch
// ---------------------------------------------------------------------------
extern "C" void kernel_launch(void* const* d_in, const int* in_sizes, int n_in,
                              void* d_out, int out_size)
{
    const float* x           = (const float*)d_in[0];   // [B, I]
    const float* prev_master = (const float*)d_in[1];   // [B, H]
    const float* prev_sub    = (const float*)d_in[2];   // [S, B, H]
    const float* gumbel      = (const float*)d_in[3];   // [B, S]
    const float* W_ih        = (const float*)d_in[4];   // [S, H, I]
    const float* W_hh        = (const float*)d_in[5];   // [S, H, H]
    const float* b_ih        = (const float*)d_in[6];   // [S, H]
    const float* b_hh        = (const float*)d_in[7];   // [S, H]
    const float* gate_W      = (const float*)d_in[8];   // [S, H]
    const float* gate_b      = (const float*)d_in[9];   // [S]
    const float* fusion_W    = (const float*)d_in[10];  // [H, H]
    const float* fusion_b    = (const float*)d_in[11];  // [H]
    const float* ln_g        = (const float*)d_in[12];  // [H]
    const float* ln_b        = (const float*)d_in[13];  // [H]

    float* out        = (float*)d_out;
    float* out_master = out;                                  // B*H
    float* out_gate   = out + (size_t)BSZ * HD;               // B*S
    float* out_sub    = out + (size_t)BSZ * HD + BSZ * NS;    // S*B*H

    cudaFuncSetAttribute(subcell_kernel,
                         cudaFuncAttributeMaxDynamicSharedMemorySize, SMEM_BYTES);
    cudaFuncSetAttribute(fusion_kernel,
                         cudaFuncAttributeMaxDynamicSharedMemorySize, SMEM_BYTES);

    // f32 -> f16 conversion of GEMM operands
    __half *p_x16, *p_sub16, *p_wih16, *p_whh16, *p_fw16;
    cudaGetSymbolAddress((void**)&p_x16,   g_x16);
    cudaGetSymbolAddress((void**)&p_sub16, g_sub16);
    cudaGetSymbolAddress((void**)&p_wih16, g_wih16);
    cudaGetSymbolAddress((void**)&p_whh16, g_whh16);
    cudaGetSymbolAddress((void**)&p_fw16,  g_fw16);

    cvt_f16_kernel<<<2048, 256>>>(x,        p_x16,   (size_t)BSZ * ID);
    cvt_f16_kernel<<<2048, 256>>>(prev_sub, p_sub16, (size_t)NS * BSZ * HD);
    cvt_f16_kernel<<<2048, 256>>>(W_ih,     p_wih16, (size_t)NS * HD * ID);
    cvt_f16_kernel<<<2048, 256>>>(W_hh,     p_whh16, (size_t)NS * HD * HD);
    cvt_f16_kernel<<<2048, 256>>>(fusion_W, p_fw16,  (size_t)HD * HD);

    gate_kernel<<<BSZ, 128>>>(prev_master, gumbel, gate_W, gate_b, out_gate);

    dim3 g2(HD / BN, BSZ / BM, NS);   // (16, 32, 3)
    subcell_kernel<<<g2, NTHREADS, SMEM_BYTES>>>(b_ih, b_hh, out_sub);

    dim3 g3(HD / BN, BSZ / BM);       // (16, 32)
    fusion_kernel<<<g3, NTHREADS, SMEM_BYTES>>>(fusion_b, prev_master, out_master);

    ln_kernel<<<BSZ, 256>>>(out_master, ln_g, ln_b);
}